// round 1
// baseline (speedup 1.0000x reference)
#include <cuda_runtime.h>
#include <cstddef>

#define NN 100000
#define EE 3200000

// Scratch (device globals — no allocation allowed)
__device__ float g_T0[(size_t)NN * 256];  // x@W1, later reused as [N,64] for gc3 pre-spmm
__device__ float g_H1[(size_t)NN * 256];  // relu(spmm1 + b1)
__device__ float g_T1[(size_t)NN * 64];   // H1@W2
__device__ float g_H3[(size_t)NN * 64];   // spmm2 + b2
__device__ float g_T2[(size_t)NN * 64];   // spmm3 + r

// ---------------------------------------------------------------------------
// Tiled fp32 GEMM: C[M,N] = A[M,K] @ B[K,N].  BM=BN=64, BK=16, 256 threads,
// 4x4 register micro-tile per thread. K and N must be multiples of 16/64 resp.
// ---------------------------------------------------------------------------
__global__ void gemm_tiled(const float* __restrict__ A, const float* __restrict__ B,
                           float* __restrict__ C, int M, int N, int K) {
    __shared__ float As[16][68];  // [k][m], pad to 68 (mult of 4) keeps float4 align
    __shared__ float Bs[16][68];  // [k][n]
    const int tx   = threadIdx.x;           // 0..255
    const int row0 = blockIdx.x * 64;
    const int col0 = blockIdx.y * 64;
    const int tm   = (tx >> 4) << 2;        // 0,4,...,60
    const int tn   = (tx & 15) << 2;
    const int a_m  = tx & 63;
    const int a_k  = (tx >> 6) << 2;        // 0,4,8,12
    const int b_k  = tx >> 4;               // 0..15
    const int b_n  = (tx & 15) << 2;
    const bool a_valid = (row0 + a_m) < M;

    float acc[4][4];
#pragma unroll
    for (int i = 0; i < 4; i++)
#pragma unroll
        for (int j = 0; j < 4; j++) acc[i][j] = 0.0f;

    for (int k0 = 0; k0 < K; k0 += 16) {
        float4 av = make_float4(0.f, 0.f, 0.f, 0.f);
        if (a_valid)
            av = *(const float4*)(A + (size_t)(row0 + a_m) * K + k0 + a_k);
        As[a_k + 0][a_m] = av.x;
        As[a_k + 1][a_m] = av.y;
        As[a_k + 2][a_m] = av.z;
        As[a_k + 3][a_m] = av.w;

        float4 bv = *(const float4*)(B + (size_t)(k0 + b_k) * N + col0 + b_n);
        *(float4*)&Bs[b_k][b_n] = bv;
        __syncthreads();

#pragma unroll
        for (int kk = 0; kk < 16; kk++) {
            float4 a4 = *(const float4*)&As[kk][tm];
            float4 b4 = *(const float4*)&Bs[kk][tn];
            float av_[4] = {a4.x, a4.y, a4.z, a4.w};
            float bv_[4] = {b4.x, b4.y, b4.z, b4.w};
#pragma unroll
            for (int i = 0; i < 4; i++)
#pragma unroll
                for (int j = 0; j < 4; j++) acc[i][j] += av_[i] * bv_[j];
        }
        __syncthreads();
    }

#pragma unroll
    for (int i = 0; i < 4; i++) {
        int r = row0 + tm + i;
        if (r < M) {
            float4 o = make_float4(acc[i][0], acc[i][1], acc[i][2], acc[i][3]);
            *(float4*)(C + (size_t)r * N + col0 + tn) = o;
        }
    }
}

// out[i*d + j] = bias[j]   (d is a power of 2)
__global__ void init_bias(float* __restrict__ out, const float* __restrict__ b,
                          size_t total, int dmask) {
    size_t i = (size_t)blockIdx.x * blockDim.x + threadIdx.x;
    if (i < total) out[i] = b[i & dmask];
}

__global__ void relu_vec4(float4* __restrict__ x, size_t n4) {
    size_t i = (size_t)blockIdx.x * blockDim.x + threadIdx.x;
    if (i < n4) {
        float4 v = x[i];
        v.x = fmaxf(v.x, 0.f); v.y = fmaxf(v.y, 0.f);
        v.z = fmaxf(v.z, 0.f); v.w = fmaxf(v.w, 0.f);
        x[i] = v;
    }
}

// SpMM d=256: one warp per edge; lane handles 2 float4 (8 cols).
__global__ void spmm256(const float* __restrict__ H, const int* __restrict__ src,
                        const int* __restrict__ dst, const float* __restrict__ w,
                        float* __restrict__ out) {
    int warp = (int)(((size_t)blockIdx.x * blockDim.x + threadIdx.x) >> 5);
    int lane = threadIdx.x & 31;
    if (warp >= EE) return;
    int s = src[warp], d = dst[warp];
    float ww = w[warp];
    const float4* hp = (const float4*)(H + (size_t)s * 256);
    float* op = out + (size_t)d * 256;
#pragma unroll
    for (int i = 0; i < 2; i++) {
        int c4 = lane + 32 * i;
        float4 v = hp[c4];
        int c = c4 * 4;
        atomicAdd(op + c + 0, v.x * ww);
        atomicAdd(op + c + 1, v.y * ww);
        atomicAdd(op + c + 2, v.z * ww);
        atomicAdd(op + c + 3, v.w * ww);
    }
}

// SpMM d=64: one warp per edge; lane handles one float2 (2 cols).
__global__ void spmm64(const float* __restrict__ H, const int* __restrict__ src,
                       const int* __restrict__ dst, const float* __restrict__ w,
                       float* __restrict__ out) {
    int warp = (int)(((size_t)blockIdx.x * blockDim.x + threadIdx.x) >> 5);
    int lane = threadIdx.x & 31;
    if (warp >= EE) return;
    int s = src[warp], d = dst[warp];
    float ww = w[warp];
    const float2* hp = (const float2*)(H + (size_t)s * 64);
    float* op = out + (size_t)d * 64;
    float2 v = hp[lane];
    atomicAdd(op + 2 * lane + 0, v.x * ww);
    atomicAdd(op + 2 * lane + 1, v.y * ww);
}

// log_softmax over rows of 64: one warp per row.
__global__ void logsoftmax64(const float* __restrict__ in, float* __restrict__ out,
                             int n) {
    int row  = (int)(((size_t)blockIdx.x * blockDim.x + threadIdx.x) >> 5);
    int lane = threadIdx.x & 31;
    if (row >= n) return;
    const float* p = in + (size_t)row * 64;
    float v0 = p[lane], v1 = p[lane + 32];
    float m = fmaxf(v0, v1);
#pragma unroll
    for (int o = 16; o; o >>= 1) m = fmaxf(m, __shfl_xor_sync(0xFFFFFFFFu, m, o));
    float s = __expf(v0 - m) + __expf(v1 - m);
#pragma unroll
    for (int o = 16; o; o >>= 1) s += __shfl_xor_sync(0xFFFFFFFFu, s, o);
    float lg = m + logf(s);
    out[(size_t)row * 64 + lane]      = v0 - lg;
    out[(size_t)row * 64 + lane + 32] = v1 - lg;
}

extern "C" void kernel_launch(void* const* d_in, const int* in_sizes, int n_in,
                              void* d_out, int out_size) {
    const float* x  = (const float*)d_in[0];
    const int*   src = (const int*)d_in[1];
    const int*   dst = (const int*)d_in[2];
    const float* ew = (const float*)d_in[3];
    const float* W1 = (const float*)d_in[4];
    const float* b1 = (const float*)d_in[5];
    const float* W2 = (const float*)d_in[6];
    const float* b2 = (const float*)d_in[7];
    const float* W3 = (const float*)d_in[8];
    const float* r  = (const float*)d_in[9];
    float* out = (float*)d_out;

    float *t0, *h1, *t1, *h3, *t2;
    cudaGetSymbolAddress((void**)&t0, g_T0);
    cudaGetSymbolAddress((void**)&h1, g_H1);
    cudaGetSymbolAddress((void**)&t1, g_T1);
    cudaGetSymbolAddress((void**)&h3, g_H3);
    cudaGetSymbolAddress((void**)&t2, g_T2);

    const int MB = (NN + 63) / 64;  // 1563 row-tiles
    const int eblocks = EE / 8;     // 8 warps (edges) per 256-thread block

    // gc1: T0 = x @ W1 ; H1 = relu(spmm(T0) + b1)
    gemm_tiled<<<dim3(MB, 4), 256>>>(x, W1, t0, NN, 256, 512);
    {
        size_t tot = (size_t)NN * 256;
        init_bias<<<(unsigned)((tot + 255) / 256), 256>>>(h1, b1, tot, 255);
    }
    spmm256<<<eblocks, 256>>>(t0, src, dst, ew, h1);
    relu_vec4<<<(unsigned)(((size_t)NN * 64 + 255) / 256), 256>>>((float4*)h1,
                                                                  (size_t)NN * 64);

    // gc2: T1 = H1 @ W2 ; H3 = spmm(T1) + b2
    gemm_tiled<<<dim3(MB, 1), 256>>>(h1, W2, t1, NN, 64, 256);
    {
        size_t tot = (size_t)NN * 64;
        init_bias<<<(unsigned)((tot + 255) / 256), 256>>>(h3, b2, tot, 63);
    }
    spmm64<<<eblocks, 256>>>(t1, src, dst, ew, h3);

    // gc3: T0(reused) = H3 @ W3 ; T2 = spmm(T0) + r
    gemm_tiled<<<dim3(MB, 1), 256>>>(h3, W3, t0, NN, 64, 64);
    {
        size_t tot = (size_t)NN * 64;
        init_bias<<<(unsigned)((tot + 255) / 256), 256>>>(t2, r, tot, 63);
    }
    spmm64<<<eblocks, 256>>>(t0, src, dst, ew, t2);

    // log_softmax -> d_out
    logsoftmax64<<<(unsigned)(((size_t)NN * 32 + 255) / 256), 256>>>(t2, out, NN);
}

// round 2
// speedup vs baseline: 3.9015x; 3.9015x over previous
#include <cuda_runtime.h>
#include <mma.h>
#include <cstddef>
using namespace nvcuda;

#define NN 100000
#define EE 3200000
#define NPAD 100096            // 782 * 128
#define SCAN_B 98              // ceil(NN/1024)

// ---------------- scratch (device globals; zero-initialized) ----------------
__device__ float g_T0[(size_t)NPAD * 256];  // x@W1 (d=256); reused as [NPAD,64] for h3@W3
__device__ float g_H1[(size_t)NPAD * 256];  // spmm1 + b1 (relu fused into GEMM2 A-load)
__device__ float g_T1[(size_t)NPAD * 64];   // relu(H1)@W2
__device__ float g_H3[(size_t)NPAD * 64];   // spmm2 + b2
__device__ int   g_deg[NN];
__device__ int   g_incl[SCAN_B * 1024];
__device__ int   g_part[SCAN_B + 1];
__device__ int   g_rowptr[NN + 1];
__device__ int   g_wofs[NN];
__device__ int   g_esrc[EE];
__device__ float g_ewt[EE];

// ---------------------------------------------------------------------------
// tf32 wmma GEMM: C[M,N] = op(A)[M,K] @ B[K,N].  BM=128 BN=64 BK=32,
// 256 threads = 8 warps (4x2), each warp 32x32 via 2x2 m16n16k8 frags.
// K % 32 == 0, N % 64 == 0. C rows are stored unguarded (C is padded).
// ---------------------------------------------------------------------------
template <bool RELU_A>
__global__ void gemm_tf32(const float* __restrict__ A, const float* __restrict__ B,
                          float* __restrict__ C, int M, int N, int K) {
    __shared__ float As[128][36];
    __shared__ float Bs[32][68];
    const int tid = threadIdx.x;
    const int wid = tid >> 5;
    const int wm = wid & 3;        // 0..3 -> 32-row slab
    const int wn = wid >> 2;       // 0..1 -> 32-col slab
    const int row0 = blockIdx.x * 128;
    const int col0 = blockIdx.y * 64;

    wmma::fragment<wmma::accumulator, 16, 16, 8, float> fc[2][2];
#pragma unroll
    for (int i = 0; i < 2; i++)
#pragma unroll
        for (int j = 0; j < 2; j++) wmma::fill_fragment(fc[i][j], 0.0f);

    for (int k0 = 0; k0 < K; k0 += 32) {
        // A tile: 128x32, 4 float4 per thread
#pragma unroll
        for (int i = 0; i < 4; i++) {
            int r = (tid >> 3) + i * 32;
            int c4 = tid & 7;
            int gr = row0 + r;
            float4 v = make_float4(0.f, 0.f, 0.f, 0.f);
            if (gr < M) v = *(const float4*)(A + (size_t)gr * K + k0 + c4 * 4);
            if (RELU_A) {
                v.x = fmaxf(v.x, 0.f); v.y = fmaxf(v.y, 0.f);
                v.z = fmaxf(v.z, 0.f); v.w = fmaxf(v.w, 0.f);
            }
            *(float4*)&As[r][c4 * 4] = v;
        }
        // B tile: 32x64, 2 float4 per thread
#pragma unroll
        for (int i = 0; i < 2; i++) {
            int r = (tid >> 4) + i * 16;
            int c4 = tid & 15;
            float4 v = *(const float4*)(B + (size_t)(k0 + r) * N + col0 + c4 * 4);
            *(float4*)&Bs[r][c4 * 4] = v;
        }
        __syncthreads();

#pragma unroll
        for (int kk = 0; kk < 32; kk += 8) {
            wmma::fragment<wmma::matrix_a, 16, 16, 8, wmma::precision::tf32,
                           wmma::row_major> fa[2];
            wmma::fragment<wmma::matrix_b, 16, 16, 8, wmma::precision::tf32,
                           wmma::row_major> fb[2];
#pragma unroll
            for (int i = 0; i < 2; i++) {
                wmma::load_matrix_sync(fa[i], &As[wm * 32 + i * 16][kk], 36);
#pragma unroll
                for (int t = 0; t < fa[i].num_elements; t++)
                    fa[i].x[t] = wmma::__float_to_tf32(fa[i].x[t]);
                wmma::load_matrix_sync(fb[i], &Bs[kk][wn * 32 + i * 16], 68);
#pragma unroll
                for (int t = 0; t < fb[i].num_elements; t++)
                    fb[i].x[t] = wmma::__float_to_tf32(fb[i].x[t]);
            }
#pragma unroll
            for (int i = 0; i < 2; i++)
#pragma unroll
                for (int j = 0; j < 2; j++)
                    wmma::mma_sync(fc[i][j], fa[i], fb[j], fc[i][j]);
        }
        __syncthreads();
    }

#pragma unroll
    for (int i = 0; i < 2; i++) {
        int r = row0 + wm * 32 + i * 16;
#pragma unroll
        for (int j = 0; j < 2; j++)
            wmma::store_matrix_sync(C + (size_t)r * N + col0 + wn * 32 + j * 16,
                                    fc[i][j], N, wmma::mem_row_major);
    }
}

// ---------------------------- CSR construction -----------------------------
__global__ void hist_kernel(const int* __restrict__ dst, int* __restrict__ deg) {
    int i = blockIdx.x * blockDim.x + threadIdx.x;
    if (i < EE) atomicAdd(&deg[dst[i]], 1);
}

__global__ void scan_block(const int* __restrict__ deg, int* __restrict__ incl,
                           int* __restrict__ part) {
    __shared__ int s[1024];
    int tid = threadIdx.x;
    int i = blockIdx.x * 1024 + tid;
    int v = (i < NN) ? deg[i] : 0;
    s[tid] = v;
    __syncthreads();
#pragma unroll
    for (int o = 1; o < 1024; o <<= 1) {
        int t = (tid >= o) ? s[tid - o] : 0;
        __syncthreads();
        if (tid >= o) s[tid] += t;
        __syncthreads();
    }
    incl[i] = s[tid];
    if (tid == 1023) part[blockIdx.x] = s[1023];
}

__global__ void scan_partials(int* __restrict__ part) {
    if (threadIdx.x == 0) {
        int run = 0;
        for (int i = 0; i < SCAN_B; i++) {
            int t = part[i];
            part[i] = run;
            run += t;
        }
    }
}

__global__ void scan_finalize(const int* __restrict__ deg, const int* __restrict__ incl,
                              const int* __restrict__ part, int* __restrict__ rowptr,
                              int* __restrict__ wofs) {
    int i = blockIdx.x * blockDim.x + threadIdx.x;
    if (i < NN) {
        int excl = incl[i] - deg[i] + part[i >> 10];
        rowptr[i] = excl;
        wofs[i] = excl;
    }
    if (i == 0) rowptr[NN] = EE;
}

__global__ void scatter_edges(const int* __restrict__ src, const int* __restrict__ dst,
                              const float* __restrict__ w, int* __restrict__ wofs,
                              int* __restrict__ esrc, float* __restrict__ ewt) {
    int i = blockIdx.x * blockDim.x + threadIdx.x;
    if (i < EE) {
        int pos = atomicAdd(&wofs[dst[i]], 1);
        esrc[pos] = src[i];
        ewt[pos] = w[i];
    }
}

// ------------------------- CSR SpMM (no atomics) ---------------------------
// d=256: one warp per node. Lane holds cols [4*lane..4*lane+3] and [128+4*lane..].
__global__ void spmm_csr_256(const float* __restrict__ H, const int* __restrict__ rowptr,
                             const int* __restrict__ esrc, const float* __restrict__ ewt,
                             const float* __restrict__ bias, float* __restrict__ out) {
    int node = (blockIdx.x * blockDim.x + threadIdx.x) >> 5;
    int lane = threadIdx.x & 31;
    if (node >= NN) return;
    int beg = rowptr[node], end = rowptr[node + 1];
    float4 a0 = make_float4(0.f, 0.f, 0.f, 0.f);
    float4 a1 = make_float4(0.f, 0.f, 0.f, 0.f);
    int e = beg;
    for (; e + 1 < end; e += 2) {
        int s0 = esrc[e], s1 = esrc[e + 1];
        float w0 = ewt[e], w1 = ewt[e + 1];
        const float4* h0 = (const float4*)(H + (size_t)s0 * 256);
        const float4* h1 = (const float4*)(H + (size_t)s1 * 256);
        float4 u0 = h0[lane], u1 = h0[lane + 32];
        float4 v0 = h1[lane], v1 = h1[lane + 32];
        a0.x += u0.x * w0 + v0.x * w1; a0.y += u0.y * w0 + v0.y * w1;
        a0.z += u0.z * w0 + v0.z * w1; a0.w += u0.w * w0 + v0.w * w1;
        a1.x += u1.x * w0 + v1.x * w1; a1.y += u1.y * w0 + v1.y * w1;
        a1.z += u1.z * w0 + v1.z * w1; a1.w += u1.w * w0 + v1.w * w1;
    }
    if (e < end) {
        int s0 = esrc[e];
        float w0 = ewt[e];
        const float4* h0 = (const float4*)(H + (size_t)s0 * 256);
        float4 u0 = h0[lane], u1 = h0[lane + 32];
        a0.x += u0.x * w0; a0.y += u0.y * w0; a0.z += u0.z * w0; a0.w += u0.w * w0;
        a1.x += u1.x * w0; a1.y += u1.y * w0; a1.z += u1.z * w0; a1.w += u1.w * w0;
    }
    const float4* bb = (const float4*)bias;
    float4 b0 = bb[lane], b1 = bb[lane + 32];
    a0.x += b0.x; a0.y += b0.y; a0.z += b0.z; a0.w += b0.w;
    a1.x += b1.x; a1.y += b1.y; a1.z += b1.z; a1.w += b1.w;
    float4* op = (float4*)(out + (size_t)node * 256);
    op[lane] = a0;
    op[lane + 32] = a1;
}

// d=64: one warp per node; lane holds cols [2*lane, 2*lane+1].
// MODE 0: out = acc + bias.  MODE 1: out = log_softmax(acc + bias).
template <int MODE>
__global__ void spmm_csr_64(const float* __restrict__ H, const int* __restrict__ rowptr,
                            const int* __restrict__ esrc, const float* __restrict__ ewt,
                            const float* __restrict__ bias, float* __restrict__ out) {
    int node = (blockIdx.x * blockDim.x + threadIdx.x) >> 5;
    int lane = threadIdx.x & 31;
    if (node >= NN) return;
    int beg = rowptr[node], end = rowptr[node + 1];
    float ax = 0.f, ay = 0.f;
    int e = beg;
    for (; e + 1 < end; e += 2) {
        int s0 = esrc[e], s1 = esrc[e + 1];
        float w0 = ewt[e], w1 = ewt[e + 1];
        float2 u = ((const float2*)(H + (size_t)s0 * 64))[lane];
        float2 v = ((const float2*)(H + (size_t)s1 * 64))[lane];
        ax += u.x * w0 + v.x * w1;
        ay += u.y * w0 + v.y * w1;
    }
    if (e < end) {
        float w0 = ewt[e];
        float2 u = ((const float2*)(H + (size_t)esrc[e] * 64))[lane];
        ax += u.x * w0;
        ay += u.y * w0;
    }
    float2 b = ((const float2*)bias)[lane];
    ax += b.x;
    ay += b.y;
    if (MODE == 0) {
        ((float2*)(out + (size_t)node * 64))[lane] = make_float2(ax, ay);
    } else {
        float m = fmaxf(ax, ay);
#pragma unroll
        for (int o = 16; o; o >>= 1) m = fmaxf(m, __shfl_xor_sync(0xFFFFFFFFu, m, o));
        float s = __expf(ax - m) + __expf(ay - m);
#pragma unroll
        for (int o = 16; o; o >>= 1) s += __shfl_xor_sync(0xFFFFFFFFu, s, o);
        float lg = m + logf(s);
        ((float2*)(out + (size_t)node * 64))[lane] = make_float2(ax - lg, ay - lg);
    }
}

// ---------------------------------------------------------------------------
extern "C" void kernel_launch(void* const* d_in, const int* in_sizes, int n_in,
                              void* d_out, int out_size) {
    const float* x   = (const float*)d_in[0];
    const int*   src = (const int*)d_in[1];
    const int*   dst = (const int*)d_in[2];
    const float* ew  = (const float*)d_in[3];
    const float* W1  = (const float*)d_in[4];
    const float* b1  = (const float*)d_in[5];
    const float* W2  = (const float*)d_in[6];
    const float* b2  = (const float*)d_in[7];
    const float* W3  = (const float*)d_in[8];
    const float* r   = (const float*)d_in[9];
    float* out = (float*)d_out;

    float *t0, *h1, *t1, *h3;
    int *deg, *incl, *part, *rowptr, *wofs, *esrc;
    float* ewt;
    cudaGetSymbolAddress((void**)&t0, g_T0);
    cudaGetSymbolAddress((void**)&h1, g_H1);
    cudaGetSymbolAddress((void**)&t1, g_T1);
    cudaGetSymbolAddress((void**)&h3, g_H3);
    cudaGetSymbolAddress((void**)&deg, g_deg);
    cudaGetSymbolAddress((void**)&incl, g_incl);
    cudaGetSymbolAddress((void**)&part, g_part);
    cudaGetSymbolAddress((void**)&rowptr, g_rowptr);
    cudaGetSymbolAddress((void**)&wofs, g_wofs);
    cudaGetSymbolAddress((void**)&esrc, g_esrc);
    cudaGetSymbolAddress((void**)&ewt, g_ewt);

    const int EB = (EE + 255) / 256;            // 12500
    const int NB = (NN + 255) / 256;            // 391
    const int WB = (int)(((size_t)NN * 32 + 255) / 256);  // warp-per-node grids
    const int MB = NPAD / 128;                  // 782

    // ---- CSR build (by dst) ----
    cudaMemsetAsync(deg, 0, NN * sizeof(int));
    hist_kernel<<<EB, 256>>>(dst, deg);
    scan_block<<<SCAN_B, 1024>>>(deg, incl, part);
    scan_partials<<<1, 32>>>(part);
    scan_finalize<<<NB, 256>>>(deg, incl, part, rowptr, wofs);
    scatter_edges<<<EB, 256>>>(src, dst, ew, wofs, esrc, ewt);

    // ---- gc1: T0 = x @ W1 ; H1 = spmm(T0) + b1  (relu deferred to gemm2) ----
    gemm_tf32<false><<<dim3(MB, 4), 256>>>(x, W1, t0, NN, 256, 512);
    spmm_csr_256<<<WB, 256>>>(t0, rowptr, esrc, ewt, b1, h1);

    // ---- gc2: T1 = relu(H1) @ W2 ; H3 = spmm(T1) + b2 ----
    gemm_tf32<true><<<dim3(MB, 1), 256>>>(h1, W2, t1, NPAD, 64, 256);
    spmm_csr_64<0><<<WB, 256>>>(t1, rowptr, esrc, ewt, b2, h3);

    // ---- gc3: T0(reused, 64-wide) = H3 @ W3 ; out = log_softmax(spmm + r) ----
    gemm_tf32<false><<<dim3(MB, 1), 256>>>(h3, W3, t0, NPAD, 64, 64);
    spmm_csr_64<1><<<WB, 256>>>(t0, rowptr, esrc, ewt, r, out);
}

// round 4
// speedup vs baseline: 6.9250x; 1.7749x over previous
#include <cuda_runtime.h>
#include <cuda_fp16.h>
#include <mma.h>
#include <cstddef>
#include <cstdint>
using namespace nvcuda;

#define NN 100000
#define EE 3200000
#define NPAD 100096            // 782 * 128
#define SCAN_B 98              // ceil(NN/1024)

// ---------------- scratch (device globals; zero-initialized) ----------------
__device__ __half g_Xh[(size_t)NPAD * 512];   // fp16 copy of x (padded rows = 0)
__device__ __half g_T0h[(size_t)NPAD * 256];  // x@W1 ; reused as [NPAD,64] for h3@W3
__device__ __half g_H1h[(size_t)NPAD * 256];  // relu(spmm1 + b1)
__device__ __half g_T1h[(size_t)NPAD * 64];   // H1@W2
__device__ __half g_H3h[(size_t)NPAD * 64];   // spmm2 + b2
__device__ __half g_W1h[512 * 256];
__device__ __half g_W2h[256 * 64];
__device__ __half g_W3h[64 * 64];
__device__ int    g_deg[NN];
__device__ int    g_incl[SCAN_B * 1024];
__device__ int    g_part[SCAN_B + 1];
__device__ int    g_rowptr[NN + 1];
__device__ int    g_wofs[NN];
__device__ int2   g_edge[EE];                 // {src, weight-bits}

// ------------------------------ helpers ------------------------------------
__device__ __forceinline__ void cp16(void* s, const void* g) {
    uint32_t sa = (uint32_t)__cvta_generic_to_shared(s);
    asm volatile("cp.async.cg.shared.global [%0], [%1], 16;" :: "r"(sa), "l"(g));
}
__device__ __forceinline__ void cp_commit() {
    asm volatile("cp.async.commit_group;");
}
template <int P>
__device__ __forceinline__ void cp_wait() {
    asm volatile("cp.async.wait_group %0;" :: "n"(P));
}

// fp32 -> fp16 conversion (vectorized by 4)
__global__ void conv_f2h(const float4* __restrict__ in, __half* __restrict__ out,
                         size_t n4) {
    size_t i = (size_t)blockIdx.x * blockDim.x + threadIdx.x;
    if (i < n4) {
        float4 v = in[i];
        __half2* o = (__half2*)(out + i * 4);
        o[0] = __floats2half2_rn(v.x, v.y);
        o[1] = __floats2half2_rn(v.z, v.w);
    }
}

// ---------------------------------------------------------------------------
// fp16 wmma GEMM with cp.async double buffering.
// C[M,N](fp16) = A[M,K](fp16) @ B[K,N](fp16).  BM=128, BN=template, BK=32.
// 256 threads = 8 warps (4 in M x 2 in N); warp tile 32 x BN/2.
// A must have >= gridDim.x*128 rows (zero-padded scratch); K%32==0.
// ---------------------------------------------------------------------------
template <int BN>
__launch_bounds__(256, 2)
__global__ void gemm_h(const __half* __restrict__ A, const __half* __restrict__ B,
                       __half* __restrict__ C, int K, int N) {
    constexpr int FRAGN = BN / 32;       // N-frags per warp
    constexpr int SA = 40;               // A smem row stride (halfs)
    constexpr int SB = BN + 8;
    __shared__ __half As[2][128 * SA];
    __shared__ __half Bs[2][32 * SB];

    const int tid = threadIdx.x;
    const int wid = tid >> 5;
    const int wm = wid & 3;
    const int wn = wid >> 2;
    const int row0 = blockIdx.x * 128;
    const int col0 = blockIdx.y * BN;

    const int ar = tid >> 2;             // 0..63
    const int ac = (tid & 3) * 8;

    wmma::fragment<wmma::accumulator, 16, 16, 16, float> acc[2][FRAGN];
#pragma unroll
    for (int i = 0; i < 2; i++)
#pragma unroll
        for (int j = 0; j < FRAGN; j++) wmma::fill_fragment(acc[i][j], 0.0f);

    const int KT = K / 32;

    auto issue = [&](int buf, int k0) {
        const __half* Ag = A + (size_t)(row0 + ar) * K + k0 + ac;
        cp16(&As[buf][ar * SA + ac], Ag);
        cp16(&As[buf][(ar + 64) * SA + ac], Ag + (size_t)64 * K);
        if (BN == 128) {
            int br = tid >> 4, bc = (tid & 15) * 8;
            cp16(&Bs[buf][br * SB + bc], B + (size_t)(k0 + br) * N + col0 + bc);
            cp16(&Bs[buf][(br + 16) * SB + bc],
                 B + (size_t)(k0 + br + 16) * N + col0 + bc);
        } else {
            int br = tid >> 3, bc = (tid & 7) * 8;
            cp16(&Bs[buf][br * SB + bc], B + (size_t)(k0 + br) * N + col0 + bc);
        }
    };

    issue(0, 0);
    cp_commit();

    for (int kt = 0; kt < KT; kt++) {
        int buf = kt & 1;
        if (kt + 1 < KT) {
            issue(buf ^ 1, (kt + 1) * 32);
            cp_commit();
            cp_wait<1>();
        } else {
            cp_wait<0>();
        }
        __syncthreads();
#pragma unroll
        for (int kk = 0; kk < 32; kk += 16) {
            wmma::fragment<wmma::matrix_a, 16, 16, 16, __half, wmma::row_major> fa[2];
            wmma::fragment<wmma::matrix_b, 16, 16, 16, __half, wmma::row_major> fb[FRAGN];
#pragma unroll
            for (int i = 0; i < 2; i++)
                wmma::load_matrix_sync(fa[i], &As[buf][(wm * 32 + i * 16) * SA + kk], SA);
#pragma unroll
            for (int j = 0; j < FRAGN; j++)
                wmma::load_matrix_sync(fb[j], &Bs[buf][kk * SB + wn * (BN / 2) + j * 16], SB);
#pragma unroll
            for (int i = 0; i < 2; i++)
#pragma unroll
                for (int j = 0; j < FRAGN; j++)
                    wmma::mma_sync(acc[i][j], fa[i], fb[j], acc[i][j]);
        }
        __syncthreads();
    }

    // epilogue: convert f32 accum -> f16 frag (same per-thread element order) and store
#pragma unroll
    for (int i = 0; i < 2; i++) {
        int r = row0 + wm * 32 + i * 16;
#pragma unroll
        for (int j = 0; j < FRAGN; j++) {
            wmma::fragment<wmma::accumulator, 16, 16, 16, __half> hf;
#pragma unroll
            for (int t = 0; t < hf.num_elements; t++)
                hf.x[t] = __float2half(acc[i][j].x[t]);
            wmma::store_matrix_sync(C + (size_t)r * N + col0 + wn * (BN / 2) + j * 16,
                                    hf, N, wmma::mem_row_major);
        }
    }
}

// ---------------------------- CSR construction -----------------------------
__global__ void hist_kernel(const int* __restrict__ dst, int* __restrict__ deg) {
    int i = blockIdx.x * blockDim.x + threadIdx.x;
    if (i < EE) atomicAdd(&deg[dst[i]], 1);
}

__global__ void scan_block(const int* __restrict__ deg, int* __restrict__ incl,
                           int* __restrict__ part) {
    __shared__ int s[1024];
    int tid = threadIdx.x;
    int i = blockIdx.x * 1024 + tid;
    int v = (i < NN) ? deg[i] : 0;
    s[tid] = v;
    __syncthreads();
#pragma unroll
    for (int o = 1; o < 1024; o <<= 1) {
        int t = (tid >= o) ? s[tid - o] : 0;
        __syncthreads();
        if (tid >= o) s[tid] += t;
        __syncthreads();
    }
    incl[i] = s[tid];
    if (tid == 1023) part[blockIdx.x] = s[1023];
}

__global__ void scan_partials(int* __restrict__ part) {
    if (threadIdx.x == 0) {
        int run = 0;
        for (int i = 0; i < SCAN_B; i++) {
            int t = part[i];
            part[i] = run;
            run += t;
        }
    }
}

__global__ void scan_finalize(const int* __restrict__ deg, const int* __restrict__ incl,
                              const int* __restrict__ part, int* __restrict__ rowptr,
                              int* __restrict__ wofs) {
    int i = blockIdx.x * blockDim.x + threadIdx.x;
    if (i < NN) {
        int excl = incl[i] - deg[i] + part[i >> 10];
        rowptr[i] = excl;
        wofs[i] = excl;
    }
    if (i == 0) rowptr[NN] = EE;
}

__global__ void scatter_edges(const int* __restrict__ src, const int* __restrict__ dst,
                              const float* __restrict__ w, int* __restrict__ wofs,
                              int2* __restrict__ edge) {
    int i = blockIdx.x * blockDim.x + threadIdx.x;
    if (i < EE) {
        int pos = atomicAdd(&wofs[dst[i]], 1);
        edge[pos] = make_int2(src[i], __float_as_int(w[i]));
    }
}

// ------------------------- CSR SpMM (fp16, no atomics) ----------------------
// d=256: one warp per node, lane holds cols [8*lane, 8*lane+8). +bias, relu, fp16 out.
__global__ void spmm256h(const __half* __restrict__ H, const int* __restrict__ rowptr,
                         const int2* __restrict__ edge, const float* __restrict__ bias,
                         __half* __restrict__ out) {
    int node = (blockIdx.x * blockDim.x + threadIdx.x) >> 5;
    int lane = threadIdx.x & 31;
    if (node >= NN) return;
    int beg = rowptr[node], end = rowptr[node + 1];
    float a[8];
#pragma unroll
    for (int k = 0; k < 8; k++) a[k] = 0.f;

    for (int e = beg; e < end; e++) {
        int2 ed = edge[e];
        float w = __int_as_float(ed.y);
        uint4 v = *(const uint4*)(H + (size_t)ed.x * 256 + lane * 8);
        const __half2* h2 = (const __half2*)&v;
#pragma unroll
        for (int k = 0; k < 4; k++) {
            float2 f = __half22float2(h2[k]);
            a[2 * k + 0] += w * f.x;
            a[2 * k + 1] += w * f.y;
        }
    }
    uint4 o;
    __half2* o2 = (__half2*)&o;
#pragma unroll
    for (int k = 0; k < 4; k++) {
        float bx = bias[lane * 8 + 2 * k];
        float by = bias[lane * 8 + 2 * k + 1];
        float vx = fmaxf(a[2 * k] + bx, 0.f);
        float vy = fmaxf(a[2 * k + 1] + by, 0.f);
        o2[k] = __floats2half2_rn(vx, vy);
    }
    *(uint4*)(out + (size_t)node * 256 + lane * 8) = o;
}

// d=64: one warp per node; lane holds cols [2*lane, 2*lane+1].
// MODE 0: out(fp16) = acc + bias.  MODE 1: out(fp32) = log_softmax(acc + bias).
template <int MODE>
__global__ void spmm64h(const __half* __restrict__ H, const int* __restrict__ rowptr,
                        const int2* __restrict__ edge, const float* __restrict__ bias,
                        void* __restrict__ outv) {
    int node = (blockIdx.x * blockDim.x + threadIdx.x) >> 5;
    int lane = threadIdx.x & 31;
    if (node >= NN) return;
    int beg = rowptr[node], end = rowptr[node + 1];
    float ax = 0.f, ay = 0.f;
    int e = beg;
    for (; e + 1 < end; e += 2) {
        int2 e0 = edge[e], e1 = edge[e + 1];
        float w0 = __int_as_float(e0.y), w1 = __int_as_float(e1.y);
        float2 u = __half22float2(*(const __half2*)(H + (size_t)e0.x * 64 + lane * 2));
        float2 v = __half22float2(*(const __half2*)(H + (size_t)e1.x * 64 + lane * 2));
        ax += u.x * w0 + v.x * w1;
        ay += u.y * w0 + v.y * w1;
    }
    if (e < end) {
        int2 e0 = edge[e];
        float w0 = __int_as_float(e0.y);
        float2 u = __half22float2(*(const __half2*)(H + (size_t)e0.x * 64 + lane * 2));
        ax += u.x * w0;
        ay += u.y * w0;
    }
    ax += bias[lane * 2];
    ay += bias[lane * 2 + 1];
    if (MODE == 0) {
        ((__half2*)outv)[(size_t)node * 32 + lane] = __floats2half2_rn(ax, ay);
    } else {
        float m = fmaxf(ax, ay);
#pragma unroll
        for (int o = 16; o; o >>= 1) m = fmaxf(m, __shfl_xor_sync(0xFFFFFFFFu, m, o));
        float s = __expf(ax - m) + __expf(ay - m);
#pragma unroll
        for (int o = 16; o; o >>= 1) s += __shfl_xor_sync(0xFFFFFFFFu, s, o);
        float lg = m + logf(s);
        ((float2*)outv)[(size_t)node * 32 + lane] = make_float2(ax - lg, ay - lg);
    }
}

// ---------------------------------------------------------------------------
extern "C" void kernel_launch(void* const* d_in, const int* in_sizes, int n_in,
                              void* d_out, int out_size) {
    const float* x   = (const float*)d_in[0];
    const int*   src = (const int*)d_in[1];
    const int*   dst = (const int*)d_in[2];
    const float* ew  = (const float*)d_in[3];
    const float* W1  = (const float*)d_in[4];
    const float* b1  = (const float*)d_in[5];
    const float* W2  = (const float*)d_in[6];
    const float* b2  = (const float*)d_in[7];
    const float* W3  = (const float*)d_in[8];
    const float* r   = (const float*)d_in[9];

    __half *xh, *t0h, *h1h, *t1h, *h3h, *w1h, *w2h, *w3h;
    int *deg, *incl, *part, *rowptr, *wofs;
    int2* edge;
    cudaGetSymbolAddress((void**)&xh,  g_Xh);
    cudaGetSymbolAddress((void**)&t0h, g_T0h);
    cudaGetSymbolAddress((void**)&h1h, g_H1h);
    cudaGetSymbolAddress((void**)&t1h, g_T1h);
    cudaGetSymbolAddress((void**)&h3h, g_H3h);
    cudaGetSymbolAddress((void**)&w1h, g_W1h);
    cudaGetSymbolAddress((void**)&w2h, g_W2h);
    cudaGetSymbolAddress((void**)&w3h, g_W3h);
    cudaGetSymbolAddress((void**)&deg, g_deg);
    cudaGetSymbolAddress((void**)&incl, g_incl);
    cudaGetSymbolAddress((void**)&part, g_part);
    cudaGetSymbolAddress((void**)&rowptr, g_rowptr);
    cudaGetSymbolAddress((void**)&wofs, g_wofs);
    cudaGetSymbolAddress((void**)&edge, g_edge);

    const int EB = (EE + 255) / 256;
    const int NB = (NN + 255) / 256;
    const int WB = (int)(((size_t)NN * 32 + 255) / 256);
    const int MB = NPAD / 128;   // 782

    // ---- CSR build (by dst) ----
    cudaMemsetAsync(deg, 0, NN * sizeof(int));
    hist_kernel<<<EB, 256>>>(dst, deg);
    scan_block<<<SCAN_B, 1024>>>(deg, incl, part);
    scan_partials<<<1, 32>>>(part);
    scan_finalize<<<NB, 256>>>(deg, incl, part, rowptr, wofs);
    scatter_edges<<<EB, 256>>>(src, dst, ew, wofs, edge);

    // ---- fp16 conversions ----
    {
        size_t n4 = (size_t)NN * 512 / 4;
        conv_f2h<<<(unsigned)((n4 + 255) / 256), 256>>>((const float4*)x, xh, n4);
        conv_f2h<<<(512 * 256 / 4 + 255) / 256, 256>>>((const float4*)W1, w1h, 512 * 256 / 4);
        conv_f2h<<<(256 * 64 / 4 + 255) / 256, 256>>>((const float4*)W2, w2h, 256 * 64 / 4);
        conv_f2h<<<(64 * 64 / 4 + 255) / 256, 256>>>((const float4*)W3, w3h, 64 * 64 / 4);
    }

    // ---- gc1: T0 = x @ W1 ; H1 = relu(spmm(T0) + b1) ----
    gemm_h<128><<<dim3(MB, 2), 256>>>(xh, w1h, t0h, 512, 256);
    spmm256h<<<WB, 256>>>(t0h, rowptr, edge, b1, h1h);

    // ---- gc2: T1 = H1 @ W2 ; H3 = spmm(T1) + b2 ----
    gemm_h<64><<<dim3(MB, 1), 256>>>(h1h, w2h, t1h, 256, 64);
    spmm64h<0><<<WB, 256>>>(t1h, rowptr, edge, b2, h3h);

    // ---- gc3: T0(reused, 64-wide) = H3 @ W3 ; out = log_softmax(spmm + r) ----
    gemm_h<64><<<dim3(MB, 1), 256>>>(h3h, w3h, t0h, 64, 64);
    spmm64h<1><<<WB, 256>>>(t0h, rowptr, edge, r, d_out);
}